// round 12
// baseline (speedup 1.0000x reference)
#include <cuda_runtime.h>
#include <cuda_bf16.h>
#include <cstdint>
#include <math.h>

#define NE 8
#define NT 4096
#define ND 1024
#define NH 4096
#define SLOTP (2*NT+128)
#define BM 128
#define BN 256
#define BK 32
#define ROWW 20     // A smem words per row (16 data + 4 pad)
#define BSTR 264    // B smem words per kpair row (256 data + 8 pad)
#define STGW 13568  // words per stage (2*2560 + 2*4224)
#define SMEM_DYN (3*STGW*4)

typedef __nv_bfloat16 bf16;

__device__ int      g_topi[NT*2];
__device__ float    g_topw[NT*2];
__device__ int      g_cnt[NE];
__device__ float    g_psum[NE];
__device__ int      g_off[NE+1];
__device__ int      g_cur[NE];
__device__ int      g_list[SLOTP];
__device__ int      g_slot[NT*2];
__device__ uint32_t g_AhW[(size_t)SLOTP*(ND/2)],  g_AlW[(size_t)SLOTP*(ND/2)];
__device__ uint32_t g_W1h[(size_t)NE*(ND/2)*NH], g_W1l[(size_t)NE*(ND/2)*NH];
__device__ uint32_t g_W2h[(size_t)NE*(NH/2)*ND], g_W2l[(size_t)NE*(NH/2)*ND];
__device__ uint32_t g_HhW[(size_t)SLOTP*(NH/2)], g_HlW[(size_t)SLOTP*(NH/2)];
__device__ float    g_Y[(size_t)SLOTP*ND];

__device__ __forceinline__ uint32_t smem_u32(const void* p) {
    uint32_t a;
    asm("{ .reg .u64 t; cvta.to.shared.u64 t, %1; cvt.u32.u64 %0, t; }" : "=r"(a) : "l"(p));
    return a;
}
#define CP16(d, s) asm volatile("cp.async.cg.shared.global [%0], [%1], 16;" :: "r"(d), "l"(s))
#define CPCOMMIT() asm volatile("cp.async.commit_group;" ::: "memory")
#define CPWAIT1()  asm volatile("cp.async.wait_group 1;" ::: "memory")

#define MMA(d, a0, a1, a2, a3, b0, b1) asm volatile( \
    "mma.sync.aligned.m16n8k16.row.col.f32.bf16.bf16.f32 " \
    "{%0,%1,%2,%3}, {%4,%5,%6,%7}, {%8,%9}, {%0,%1,%2,%3};" \
    : "+f"((d)[0]),"+f"((d)[1]),"+f"((d)[2]),"+f"((d)[3]) \
    : "r"(a0),"r"(a1),"r"(a2),"r"(a3), "r"(b0),"r"(b1))

__device__ __forceinline__ uint32_t pack2(float x, float y) {
    return (uint32_t)__bfloat16_as_ushort(__float2bfloat16(x)) |
           ((uint32_t)__bfloat16_as_ushort(__float2bfloat16(y)) << 16);
}
__device__ __forceinline__ uint32_t pack2lo(float x, float y) {
    float xh = __bfloat162float(__float2bfloat16(x));
    float yh = __bfloat162float(__float2bfloat16(y));
    return pack2(x - xh, y - yh);
}

// ---------------- small kernels ----------------------------------------------
__global__ void k_init() {
    int i = threadIdx.x;
    if (i < NE) { g_cnt[i] = 0; g_psum[i] = 0.f; g_cur[i] = 0; }
}

__global__ __launch_bounds__(256) void k_router(const float* __restrict__ x,
                                                const float* __restrict__ Wg) {
    __shared__ float sW[NE * ND];
    int tid = threadIdx.x;
    for (int i = tid; i < NE * ND; i += 256) sW[i] = Wg[i];
    __syncthreads();
    int warp = tid >> 5, lane = tid & 31;
    int t = blockIdx.x * 8 + warp;
    float acc[NE];
#pragma unroll
    for (int e = 0; e < NE; e++) acc[e] = 0.f;
    const float* xr = x + (size_t)t * ND;
    for (int d = lane; d < ND; d += 32) {
        float xv = xr[d];
#pragma unroll
        for (int e = 0; e < NE; e++) acc[e] = fmaf(xv, sW[e * ND + d], acc[e]);
    }
#pragma unroll
    for (int e = 0; e < NE; e++)
#pragma unroll
        for (int o = 16; o; o >>= 1) acc[e] += __shfl_xor_sync(0xffffffffu, acc[e], o);
    if (lane == 0) {
        float mx = acc[0];
#pragma unroll
        for (int e = 1; e < NE; e++) mx = fmaxf(mx, acc[e]);
        float p[NE], Z = 0.f;
#pragma unroll
        for (int e = 0; e < NE; e++) { p[e] = expf(acc[e] - mx); Z += p[e]; }
        float inv = 1.f / Z;
#pragma unroll
        for (int e = 0; e < NE; e++) { p[e] *= inv; atomicAdd(&g_psum[e], p[e]); }
        int i0 = 0;
#pragma unroll
        for (int e = 1; e < NE; e++) if (p[e] > p[i0]) i0 = e;
        int i1 = (i0 == 0) ? 1 : 0;
#pragma unroll
        for (int e = 0; e < NE; e++) if (e != i0 && p[e] > p[i1]) i1 = e;
        float s = p[i0] + p[i1];
        g_topi[t*2] = i0; g_topi[t*2+1] = i1;
        g_topw[t*2] = p[i0] / s; g_topw[t*2+1] = p[i1] / s;
        atomicAdd(&g_cnt[i0], 1); atomicAdd(&g_cnt[i1], 1);
    }
}

__global__ void k_scan(float* __restrict__ out, int out_size) {
    if (threadIdx.x == 0) {
        int off = 0;
        for (int e = 0; e < NE; e++) { g_off[e] = off; off += g_cnt[e]; }
        g_off[NE] = off;
        float invT = 1.f / (float)NT, aux = 0.f;
        for (int e = 0; e < NE; e++) aux += ((float)g_cnt[e] * invT) * (g_psum[e] * invT);
        if (out_size > NT * ND) out[(size_t)NT * ND] = aux * (float)NE;
    }
}

__global__ void k_fill() {
    int t = blockIdx.x * blockDim.x + threadIdx.x;
    if (t >= NT) return;
#pragma unroll
    for (int k = 0; k < 2; k++) {
        int e = g_topi[t*2+k];
        int s = g_off[e] + atomicAdd(&g_cur[e], 1);
        g_list[s] = t;
        g_slot[t*2+k] = s;
    }
}

// gather + split + pair-pack x
__global__ __launch_bounds__(256) void k_gather(const float* __restrict__ x) {
    int idx = blockIdx.x * 256 + threadIdx.x;
    int slot = idx >> 7;
    int q = (idx & 127) * 8;
    int t = g_list[slot];
    const float* p = x + (size_t)t * ND + q;
    float4 v0 = *(const float4*)p;
    float4 v1 = *(const float4*)(p + 4);
    uint4 h = make_uint4(pack2(v0.x, v0.y), pack2(v0.z, v0.w),
                         pack2(v1.x, v1.y), pack2(v1.z, v1.w));
    uint4 l = make_uint4(pack2lo(v0.x, v0.y), pack2lo(v0.z, v0.w),
                         pack2lo(v1.x, v1.y), pack2lo(v1.z, v1.w));
    size_t o = (size_t)slot * (ND/2) + q/2;
    *(uint4*)&g_AhW[o] = h;
    *(uint4*)&g_AlW[o] = l;
}

// split + pair-pack W (device-side global selection — NOT host-passed symbols)
template<int K, int N, bool FIRST>
__global__ __launch_bounds__(256) void k_split(const float* __restrict__ W) {
    uint32_t* __restrict__ Wh = FIRST ? g_W1h : g_W2h;
    uint32_t* __restrict__ Wl = FIRST ? g_W1l : g_W2l;
    int e = blockIdx.y;
    int idx = blockIdx.x * 256 + threadIdx.x;
    int kp = idx / (N/4);
    int nq = (idx % (N/4)) * 4;
    const float* p = W + ((size_t)e * K + 2*kp) * N + nq;
    float4 r0 = *(const float4*)p;
    float4 r1 = *(const float4*)(p + N);
    uint4 h = make_uint4(pack2(r0.x, r1.x), pack2(r0.y, r1.y),
                         pack2(r0.z, r1.z), pack2(r0.w, r1.w));
    uint4 l = make_uint4(pack2lo(r0.x, r1.x), pack2lo(r0.y, r1.y),
                         pack2lo(r0.z, r1.z), pack2lo(r0.w, r1.w));
    size_t o = ((size_t)e * (K/2) + kp) * N + nq;
    *(uint4*)&Wh[o] = h;
    *(uint4*)&Wl[o] = l;
}

// ---------------- tensor-core grouped GEMM (cp.async 3-stage) ----------------
template<int KDIM, bool G1>
__global__ __launch_bounds__(256) void k_gemm(const float* __restrict__ bias) {
    const int KW = KDIM / 2;
    int e = blockIdx.z;
    int ne = g_cnt[e];
    if ((int)blockIdx.x * BM >= ne) return;
    int row0 = g_off[e] + blockIdx.x * BM;
    int valid = min(BM, ne - (int)blockIdx.x * BM);
    int n0 = blockIdx.y * BN;

    extern __shared__ uint32_t sm[];
    __shared__ float sbias[BN];
    uint32_t sbase = smem_u32(sm);

    int tid = threadIdx.x, wid = tid >> 5, lane = tid & 31;
    int wm2 = wid & 1, wn = wid >> 1;
    const int ldn = G1 ? NH : ND;

    sbias[tid] = bias[(size_t)e * ldn + n0 + tid];

    const uint32_t* aH = (G1 ? g_AhW : g_HhW);
    const uint32_t* aL = (G1 ? g_AlW : g_HlW);
    const uint32_t* bH = (G1 ? g_W1h : g_W2h);
    const uint32_t* bL = (G1 ? g_W1l : g_W2l);

    int am = tid >> 1, half = tid & 1;
    const uint32_t* arH = aH + (size_t)(row0 + am) * KW + half * 8;
    const uint32_t* arL = aL + (size_t)(row0 + am) * KW + half * 8;
    int bkp = tid >> 4, bt = tid & 15;
    const uint32_t* brH = bH + ((size_t)e * KW + bkp) * ldn + n0 + bt * 8;
    const uint32_t* brL = bL + ((size_t)e * KW + bkp) * ldn + n0 + bt * 8;

    uint32_t aoff = (uint32_t)(am * ROWW + half * 8) * 4u;
    uint32_t boff = (uint32_t)(bkp * BSTR + bt * 8) * 4u;

    auto load_stage = [&](int s, int kc) {
        uint32_t st = sbase + (uint32_t)s * (STGW * 4u);
        const uint32_t* pa = arH + (size_t)kc * 16;
        CP16(st + aoff, pa);          CP16(st + aoff + 16, pa + 4);
        pa = arL + (size_t)kc * 16;
        CP16(st + 10240 + aoff, pa);  CP16(st + 10240 + aoff + 16, pa + 4);
        const uint32_t* pb = brH + (size_t)(kc * 16) * ldn;
        uint32_t db = st + 20480 + boff;
        CP16(db, pb);        CP16(db + 16, pb + 4);
        CP16(db + 512, pb + 128); CP16(db + 528, pb + 132);
        pb = brL + (size_t)(kc * 16) * ldn;
        db += 16896;
        CP16(db, pb);        CP16(db + 16, pb + 4);
        CP16(db + 512, pb + 128); CP16(db + 528, pb + 132);
    };

    float acc[4][8][4];
#pragma unroll
    for (int i = 0; i < 4; i++)
#pragma unroll
        for (int j = 0; j < 8; j++)
#pragma unroll
            for (int c = 0; c < 4; c++) acc[i][j][c] = 0.f;

    load_stage(0, 0); CPCOMMIT();
    load_stage(1, 1); CPCOMMIT();

    const int NK = KDIM / BK;
    int ks3 = 0;
    for (int k = 0; k < NK; k++) {
        CPWAIT1();
        __syncthreads();
        if (k + 2 < NK) load_stage((ks3 + 2) % 3, k + 2);
        CPCOMMIT();

        uint32_t* stg = sm + ks3 * STGW;
        uint32_t* sAh = stg;
        uint32_t* sAl = stg + 2560;
        uint32_t* sBh = stg + 5120;
        uint32_t* sBl = stg + 9344;

#pragma unroll
        for (int ks = 0; ks < 2; ks++) {
            int kb = ks * 8;
            uint32_t Ah[4][4], Al[4][4], Bh[8][2], Bl[8][2];
#pragma unroll
            for (int mt = 0; mt < 4; mt++) {
                int r = wm2 * 64 + mt * 16 + (lane >> 2);
                int w0 = r * ROWW + kb + (lane & 3);
                Ah[mt][0] = sAh[w0];      Ah[mt][1] = sAh[w0 + 8*ROWW];
                Ah[mt][2] = sAh[w0 + 4];  Ah[mt][3] = sAh[w0 + 8*ROWW + 4];
                Al[mt][0] = sAl[w0];      Al[mt][1] = sAl[w0 + 8*ROWW];
                Al[mt][2] = sAl[w0 + 4];  Al[mt][3] = sAl[w0 + 8*ROWW + 4];
            }
            int kp0 = kb + (lane & 3);
#pragma unroll
            for (int nb = 0; nb < 8; nb++) {
                int n = wn * 64 + nb * 8 + (lane >> 2);
                Bh[nb][0] = sBh[kp0 * BSTR + n];
                Bh[nb][1] = sBh[(kp0 + 4) * BSTR + n];
                Bl[nb][0] = sBl[kp0 * BSTR + n];
                Bl[nb][1] = sBl[(kp0 + 4) * BSTR + n];
            }
            // pass-major emission: 32 independent MMAs per pass — no acc-chained stalls
#pragma unroll
            for (int mt = 0; mt < 4; mt++)
#pragma unroll
                for (int nb = 0; nb < 8; nb++)
                    MMA(acc[mt][nb], Ah[mt][0], Ah[mt][1], Ah[mt][2], Ah[mt][3],
                        Bh[nb][0], Bh[nb][1]);
#pragma unroll
            for (int mt = 0; mt < 4; mt++)
#pragma unroll
                for (int nb = 0; nb < 8; nb++)
                    MMA(acc[mt][nb], Ah[mt][0], Ah[mt][1], Ah[mt][2], Ah[mt][3],
                        Bl[nb][0], Bl[nb][1]);
#pragma unroll
            for (int mt = 0; mt < 4; mt++)
#pragma unroll
                for (int nb = 0; nb < 8; nb++)
                    MMA(acc[mt][nb], Al[mt][0], Al[mt][1], Al[mt][2], Al[mt][3],
                        Bh[nb][0], Bh[nb][1]);
        }
        ks3 = (ks3 + 1) % 3;
    }

    // ---- epilogue ----
    int rb_ = lane >> 2;
    int cb = wn * 64 + (lane & 3) * 2;
#pragma unroll
    for (int mt = 0; mt < 4; mt++)
#pragma unroll
        for (int nb = 0; nb < 8; nb++) {
            int col = cb + nb * 8;
            float bv0 = sbias[col], bv1 = sbias[col + 1];
#pragma unroll
            for (int h = 0; h < 2; h++) {
                int rloc = wm2 * 64 + mt * 16 + h * 8 + rb_;
                if (rloc < valid) {
                    float v0 = acc[mt][nb][h*2]   + bv0;
                    float v1 = acc[mt][nb][h*2+1] + bv1;
                    if (G1) {
                        v0 = v0 / (1.f + __expf(-v0));
                        v1 = v1 / (1.f + __expf(-v1));
                        size_t go = (size_t)(row0 + rloc) * (NH/2) + (n0 + col)/2;
                        g_HhW[go] = pack2(v0, v1);
                        g_HlW[go] = pack2lo(v0, v1);
                    } else {
                        size_t go = (size_t)(row0 + rloc) * ND + n0 + col;
                        *(float2*)&g_Y[go] = make_float2(v0, v1);
                    }
                }
            }
        }
}

// ---------------- combine ----------------------------------------------------
__global__ __launch_bounds__(256) void k_combine(float* __restrict__ out) {
    int idx = blockIdx.x * 256 + threadIdx.x;
    int t = idx >> 8;
    int c = (idx & 255) << 2;
    float w0 = g_topw[t*2], w1 = g_topw[t*2+1];
    int s0 = g_slot[t*2], s1 = g_slot[t*2+1];
    float4 y0 = *(const float4*)&g_Y[(size_t)s0 * ND + c];
    float4 y1 = *(const float4*)&g_Y[(size_t)s1 * ND + c];
    float4 o;
    o.x = w0*y0.x + w1*y1.x; o.y = w0*y0.y + w1*y1.y;
    o.z = w0*y0.z + w1*y1.z; o.w = w0*y0.w + w1*y1.w;
    *(float4*)&out[(size_t)t * ND + c] = o;
}

// ---------------- launch -----------------------------------------------------
extern "C" void kernel_launch(void* const* d_in, const int* in_sizes, int n_in,
                              void* d_out, int out_size) {
    const float* x  = (const float*)d_in[0];
    const float* Wg = (const float*)d_in[1];
    const float* W1 = (const float*)d_in[2];
    const float* b1 = (const float*)d_in[3];
    const float* W2 = (const float*)d_in[4];
    const float* b2 = (const float*)d_in[5];
    float* out = (float*)d_out;

    cudaFuncSetAttribute(k_gemm<ND, true>,  cudaFuncAttributeMaxDynamicSharedMemorySize, SMEM_DYN);
    cudaFuncSetAttribute(k_gemm<NH, false>, cudaFuncAttributeMaxDynamicSharedMemorySize, SMEM_DYN);

    k_init<<<1, 32>>>();
    k_router<<<NT / 8, 256>>>(x, Wg);
    k_scan<<<1, 32>>>(out, out_size);
    k_fill<<<NT / 256, 256>>>();
    k_gather<<<2 * NT * 128 / 256, 256>>>(x);
    k_split<ND, NH, true ><<<dim3((ND/2)*(NH/4)/256, NE), 256>>>(W1);
    k_split<NH, ND, false><<<dim3((NH/2)*(ND/4)/256, NE), 256>>>(W2);
    k_gemm<ND, true><<<dim3(64, NH / BN, NE), 256, SMEM_DYN>>>(b1);
    k_gemm<NH, false><<<dim3(64, ND / BN, NE), 256, SMEM_DYN>>>(b2);
    k_combine<<<NT * ND / 4 / 256, 256>>>(out);
}

// round 14
// speedup vs baseline: 1.0196x; 1.0196x over previous
#include <cuda_runtime.h>
#include <cuda_bf16.h>
#include <cstdint>
#include <math.h>

#define NE 8
#define NT 4096
#define ND 1024
#define NH 4096
#define SLOTP (2*NT+128)
#define BM 128
#define BN 256
#define BK 32
#define ROWW 20     // A smem words per row (16 data + 4 pad)
#define BSTR 264    // B smem words per kpair row (256 data + 8 pad)
#define STGW 13568  // words per stage (2*2560 + 2*4224)
#define SMEM_DYN (3*STGW*4)

typedef __nv_bfloat16 bf16;

__device__ int      g_topi[NT*2];
__device__ float    g_topw[NT*2];
__device__ int      g_cnt[NE];
__device__ float    g_psum[NE];
__device__ int      g_off[NE+1];
__device__ int      g_cur[NE];
__device__ int      g_list[SLOTP];
__device__ int      g_slot[NT*2];
__device__ uint32_t g_AhW[(size_t)SLOTP*(ND/2)],  g_AlW[(size_t)SLOTP*(ND/2)];
__device__ uint32_t g_W1h[(size_t)NE*(ND/2)*NH], g_W1l[(size_t)NE*(ND/2)*NH];
__device__ uint32_t g_W2h[(size_t)NE*(NH/2)*ND], g_W2l[(size_t)NE*(NH/2)*ND];
__device__ uint32_t g_HhW[(size_t)SLOTP*(NH/2)], g_HlW[(size_t)SLOTP*(NH/2)];
__device__ float    g_Y[(size_t)SLOTP*ND];

__device__ __forceinline__ uint32_t smem_u32(const void* p) {
    uint32_t a;
    asm("{ .reg .u64 t; cvta.to.shared.u64 t, %1; cvt.u32.u64 %0, t; }" : "=r"(a) : "l"(p));
    return a;
}
#define CP16(d, s) asm volatile("cp.async.cg.shared.global [%0], [%1], 16;" :: "r"(d), "l"(s))
#define CPCOMMIT() asm volatile("cp.async.commit_group;" ::: "memory")
#define CPWAIT1()  asm volatile("cp.async.wait_group 1;" ::: "memory")

#define MMA(d, a0, a1, a2, a3, b0, b1) asm volatile( \
    "mma.sync.aligned.m16n8k16.row.col.f32.bf16.bf16.f32 " \
    "{%0,%1,%2,%3}, {%4,%5,%6,%7}, {%8,%9}, {%0,%1,%2,%3};" \
    : "+f"((d)[0]),"+f"((d)[1]),"+f"((d)[2]),"+f"((d)[3]) \
    : "r"(a0),"r"(a1),"r"(a2),"r"(a3), "r"(b0),"r"(b1))

__device__ __forceinline__ uint32_t pack2(float x, float y) {
    return (uint32_t)__bfloat16_as_ushort(__float2bfloat16(x)) |
           ((uint32_t)__bfloat16_as_ushort(__float2bfloat16(y)) << 16);
}
__device__ __forceinline__ uint32_t pack2lo(float x, float y) {
    float xh = __bfloat162float(__float2bfloat16(x));
    float yh = __bfloat162float(__float2bfloat16(y));
    return pack2(x - xh, y - yh);
}

// ---------------- small kernels ----------------------------------------------
__global__ void k_init() {
    int i = threadIdx.x;
    if (i < NE) { g_cnt[i] = 0; g_psum[i] = 0.f; g_cur[i] = 0; }
}

__global__ __launch_bounds__(256) void k_router(const float* __restrict__ x,
                                                const float* __restrict__ Wg) {
    __shared__ float sW[NE * ND];
    int tid = threadIdx.x;
    for (int i = tid; i < NE * ND; i += 256) sW[i] = Wg[i];
    __syncthreads();
    int warp = tid >> 5, lane = tid & 31;
    int t = blockIdx.x * 8 + warp;
    float acc[NE];
#pragma unroll
    for (int e = 0; e < NE; e++) acc[e] = 0.f;
    const float* xr = x + (size_t)t * ND;
    for (int d = lane; d < ND; d += 32) {
        float xv = xr[d];
#pragma unroll
        for (int e = 0; e < NE; e++) acc[e] = fmaf(xv, sW[e * ND + d], acc[e]);
    }
#pragma unroll
    for (int e = 0; e < NE; e++)
#pragma unroll
        for (int o = 16; o; o >>= 1) acc[e] += __shfl_xor_sync(0xffffffffu, acc[e], o);
    if (lane == 0) {
        float mx = acc[0];
#pragma unroll
        for (int e = 1; e < NE; e++) mx = fmaxf(mx, acc[e]);
        float p[NE], Z = 0.f;
#pragma unroll
        for (int e = 0; e < NE; e++) { p[e] = expf(acc[e] - mx); Z += p[e]; }
        float inv = 1.f / Z;
#pragma unroll
        for (int e = 0; e < NE; e++) { p[e] *= inv; atomicAdd(&g_psum[e], p[e]); }
        int i0 = 0;
#pragma unroll
        for (int e = 1; e < NE; e++) if (p[e] > p[i0]) i0 = e;
        int i1 = (i0 == 0) ? 1 : 0;
#pragma unroll
        for (int e = 0; e < NE; e++) if (e != i0 && p[e] > p[i1]) i1 = e;
        float s = p[i0] + p[i1];
        g_topi[t*2] = i0; g_topi[t*2+1] = i1;
        g_topw[t*2] = p[i0] / s; g_topw[t*2+1] = p[i1] / s;
        atomicAdd(&g_cnt[i0], 1); atomicAdd(&g_cnt[i1], 1);
    }
}

__global__ void k_scan(float* __restrict__ out, int out_size) {
    if (threadIdx.x == 0) {
        int off = 0;
        for (int e = 0; e < NE; e++) { g_off[e] = off; off += g_cnt[e]; }
        g_off[NE] = off;
        float invT = 1.f / (float)NT, aux = 0.f;
        for (int e = 0; e < NE; e++) aux += ((float)g_cnt[e] * invT) * (g_psum[e] * invT);
        if (out_size > NT * ND) out[(size_t)NT * ND] = aux * (float)NE;
    }
}

__global__ void k_fill() {
    int t = blockIdx.x * blockDim.x + threadIdx.x;
    if (t >= NT) return;
#pragma unroll
    for (int k = 0; k < 2; k++) {
        int e = g_topi[t*2+k];
        int s = g_off[e] + atomicAdd(&g_cur[e], 1);
        g_list[s] = t;
        g_slot[t*2+k] = s;
    }
}

// gather + split + pair-pack x
__global__ __launch_bounds__(256) void k_gather(const float* __restrict__ x) {
    int idx = blockIdx.x * 256 + threadIdx.x;
    int slot = idx >> 7;
    int q = (idx & 127) * 8;
    int t = g_list[slot];
    const float* p = x + (size_t)t * ND + q;
    float4 v0 = *(const float4*)p;
    float4 v1 = *(const float4*)(p + 4);
    uint4 h = make_uint4(pack2(v0.x, v0.y), pack2(v0.z, v0.w),
                         pack2(v1.x, v1.y), pack2(v1.z, v1.w));
    uint4 l = make_uint4(pack2lo(v0.x, v0.y), pack2lo(v0.z, v0.w),
                         pack2lo(v1.x, v1.y), pack2lo(v1.z, v1.w));
    size_t o = (size_t)slot * (ND/2) + q/2;
    *(uint4*)&g_AhW[o] = h;
    *(uint4*)&g_AlW[o] = l;
}

// split + pair-pack W (device-side global selection)
template<int K, int N, bool FIRST>
__global__ __launch_bounds__(256) void k_split(const float* __restrict__ W) {
    uint32_t* __restrict__ Wh = FIRST ? g_W1h : g_W2h;
    uint32_t* __restrict__ Wl = FIRST ? g_W1l : g_W2l;
    int e = blockIdx.y;
    int idx = blockIdx.x * 256 + threadIdx.x;
    int kp = idx / (N/4);
    int nq = (idx % (N/4)) * 4;
    const float* p = W + ((size_t)e * K + 2*kp) * N + nq;
    float4 r0 = *(const float4*)p;
    float4 r1 = *(const float4*)(p + N);
    uint4 h = make_uint4(pack2(r0.x, r1.x), pack2(r0.y, r1.y),
                         pack2(r0.z, r1.z), pack2(r0.w, r1.w));
    uint4 l = make_uint4(pack2lo(r0.x, r1.x), pack2lo(r0.y, r1.y),
                         pack2lo(r0.z, r1.z), pack2lo(r0.w, r1.w));
    size_t o = ((size_t)e * (K/2) + kp) * N + nq;
    *(uint4*)&Wh[o] = h;
    *(uint4*)&Wl[o] = l;
}

// ---------------- tensor-core grouped GEMM (512 threads, 16 warps) -----------
template<int KDIM, bool G1>
__global__ __launch_bounds__(512) void k_gemm(const float* __restrict__ bias) {
    const int KW = KDIM / 2;
    int e = blockIdx.z;
    int ne = g_cnt[e];
    if ((int)blockIdx.x * BM >= ne) return;
    int row0 = g_off[e] + blockIdx.x * BM;
    int valid = min(BM, ne - (int)blockIdx.x * BM);
    int n0 = blockIdx.y * BN;

    extern __shared__ uint32_t sm[];
    __shared__ float sbias[BN];
    uint32_t sbase = smem_u32(sm);

    int tid = threadIdx.x, wid = tid >> 5, lane = tid & 31;
    int wm = wid & 3, wn = wid >> 2;           // 4x4 warps, warp tile 32x64
    const int ldn = G1 ? NH : ND;

    if (tid < BN) sbias[tid] = bias[(size_t)e * ldn + n0 + tid];

    const uint32_t* aH = (G1 ? g_AhW : g_HhW);
    const uint32_t* aL = (G1 ? g_AlW : g_HlW);
    const uint32_t* bH = (G1 ? g_W1h : g_W2h);
    const uint32_t* bL = (G1 ? g_W1l : g_W2l);

    // A loader: thread = (row, quarter of 16 words)
    int am = tid >> 2, aw = (tid & 3) * 4;
    const uint32_t* arH = aH + (size_t)(row0 + am) * KW + aw;
    const uint32_t* arL = aL + (size_t)(row0 + am) * KW + aw;
    // B loader: warp = kpair, lane = 8-word seg
    int bkp = wid, bseg = lane * 8;
    const uint32_t* brH = bH + ((size_t)e * KW + bkp) * ldn + n0 + bseg;
    const uint32_t* brL = bL + ((size_t)e * KW + bkp) * ldn + n0 + bseg;

    uint32_t aoff = (uint32_t)(am * ROWW + aw) * 4u;
    uint32_t boff = (uint32_t)(bkp * BSTR + bseg) * 4u;

    auto load_stage = [&](int s, int kc) {
        uint32_t st = sbase + (uint32_t)s * (STGW * 4u);
        CP16(st + aoff, arH + (size_t)kc * 16);
        CP16(st + 10240 + aoff, arL + (size_t)kc * 16);
        const uint32_t* pb = brH + (size_t)(kc * 16) * ldn;
        CP16(st + 20480 + boff, pb);
        CP16(st + 20480 + boff + 16, pb + 4);
        pb = brL + (size_t)(kc * 16) * ldn;
        CP16(st + 37376 + boff, pb);
        CP16(st + 37376 + boff + 16, pb + 4);
    };

    float acc[2][8][4];
#pragma unroll
    for (int i = 0; i < 2; i++)
#pragma unroll
        for (int j = 0; j < 8; j++)
#pragma unroll
            for (int c = 0; c < 4; c++) acc[i][j][c] = 0.f;

    load_stage(0, 0); CPCOMMIT();
    load_stage(1, 1); CPCOMMIT();

    const int NK = KDIM / BK;
    int ks3 = 0;
    for (int k = 0; k < NK; k++) {
        CPWAIT1();
        __syncthreads();
        if (k + 2 < NK) load_stage((ks3 + 2) % 3, k + 2);
        CPCOMMIT();

        uint32_t* stg = sm + ks3 * STGW;
        uint32_t* sAh = stg;
        uint32_t* sAl = stg + 2560;
        uint32_t* sBh = stg + 5120;
        uint32_t* sBl = stg + 9344;

#pragma unroll
        for (int ks = 0; ks < 2; ks++) {
            int kb = ks * 8;
            uint32_t Ah[2][4], Al[2][4];
#pragma unroll
            for (int mt = 0; mt < 2; mt++) {
                int r = wm * 32 + mt * 16 + (lane >> 2);
                int w0 = r * ROWW + kb + (lane & 3);
                Ah[mt][0] = sAh[w0];      Ah[mt][1] = sAh[w0 + 8*ROWW];
                Ah[mt][2] = sAh[w0 + 4];  Ah[mt][3] = sAh[w0 + 8*ROWW + 4];
                Al[mt][0] = sAl[w0];      Al[mt][1] = sAl[w0 + 8*ROWW];
                Al[mt][2] = sAl[w0 + 4];  Al[mt][3] = sAl[w0 + 8*ROWW + 4];
            }
            int kp0 = kb + (lane & 3);
            uint32_t Bh[8][2];
#pragma unroll
            for (int nb = 0; nb < 8; nb++) {
                int n = wn * 64 + nb * 8 + (lane >> 2);
                Bh[nb][0] = sBh[kp0 * BSTR + n];
                Bh[nb][1] = sBh[(kp0 + 4) * BSTR + n];
            }
            // pass hh
#pragma unroll
            for (int mt = 0; mt < 2; mt++)
#pragma unroll
                for (int nb = 0; nb < 8; nb++)
                    MMA(acc[mt][nb], Ah[mt][0], Ah[mt][1], Ah[mt][2], Ah[mt][3],
                        Bh[nb][0], Bh[nb][1]);
            // pass lh (last use of Al, Bh)
#pragma unroll
            for (int mt = 0; mt < 2; mt++)
#pragma unroll
                for (int nb = 0; nb < 8; nb++)
                    MMA(acc[mt][nb], Al[mt][0], Al[mt][1], Al[mt][2], Al[mt][3],
                        Bh[nb][0], Bh[nb][1]);
            // pass hl (Bl loaded after Bh is dead — bounds live registers)
            uint32_t Bl[8][2];
#pragma unroll
            for (int nb = 0; nb < 8; nb++) {
                int n = wn * 64 + nb * 8 + (lane >> 2);
                Bl[nb][0] = sBl[kp0 * BSTR + n];
                Bl[nb][1] = sBl[(kp0 + 4) * BSTR + n];
            }
#pragma unroll
            for (int mt = 0; mt < 2; mt++)
#pragma unroll
                for (int nb = 0; nb < 8; nb++)
                    MMA(acc[mt][nb], Ah[mt][0], Ah[mt][1], Ah[mt][2], Ah[mt][3],
                        Bl[nb][0], Bl[nb][1]);
        }
        ks3 = (ks3 + 1) % 3;
    }

    // ---- epilogue ----
    int rb_ = lane >> 2;
    int cb = wn * 64 + (lane & 3) * 2;
#pragma unroll
    for (int mt = 0; mt < 2; mt++)
#pragma unroll
        for (int nb = 0; nb < 8; nb++) {
            int col = cb + nb * 8;
            float bv0 = sbias[col], bv1 = sbias[col + 1];
#pragma unroll
            for (int h = 0; h < 2; h++) {
                int rloc = wm * 32 + mt * 16 + h * 8 + rb_;
                if (rloc < valid) {
                    float v0 = acc[mt][nb][h*2]   + bv0;
                    float v1 = acc[mt][nb][h*2+1] + bv1;
                    if (G1) {
                        v0 = v0 / (1.f + __expf(-v0));
                        v1 = v1 / (1.f + __expf(-v1));
                        size_t go = (size_t)(row0 + rloc) * (NH/2) + (n0 + col)/2;
                        g_HhW[go] = pack2(v0, v1);
                        g_HlW[go] = pack2lo(v0, v1);
                    } else {
                        size_t go = (size_t)(row0 + rloc) * ND + n0 + col;
                        *(float2*)&g_Y[go] = make_float2(v0, v1);
                    }
                }
            }
        }
}

// ---------------- combine ----------------------------------------------------
__global__ __launch_bounds__(256) void k_combine(float* __restrict__ out) {
    int idx = blockIdx.x * 256 + threadIdx.x;
    int t = idx >> 8;
    int c = (idx & 255) << 2;
    float w0 = g_topw[t*2], w1 = g_topw[t*2+1];
    int s0 = g_slot[t*2], s1 = g_slot[t*2+1];
    float4 y0 = *(const float4*)&g_Y[(size_t)s0 * ND + c];
    float4 y1 = *(const float4*)&g_Y[(size_t)s1 * ND + c];
    float4 o;
    o.x = w0*y0.x + w1*y1.x; o.y = w0*y0.y + w1*y1.y;
    o.z = w0*y0.z + w1*y1.z; o.w = w0*y0.w + w1*y1.w;
    *(float4*)&out[(size_t)t * ND + c] = o;
}

// ---------------- launch -----------------------------------------------------
extern "C" void kernel_launch(void* const* d_in, const int* in_sizes, int n_in,
                              void* d_out, int out_size) {
    const float* x  = (const float*)d_in[0];
    const float* Wg = (const float*)d_in[1];
    const float* W1 = (const float*)d_in[2];
    const float* b1 = (const float*)d_in[3];
    const float* W2 = (const float*)d_in[4];
    const float* b2 = (const float*)d_in[5];
    float* out = (float*)d_out;

    cudaFuncSetAttribute(k_gemm<ND, true>,  cudaFuncAttributeMaxDynamicSharedMemorySize, SMEM_DYN);
    cudaFuncSetAttribute(k_gemm<NH, false>, cudaFuncAttributeMaxDynamicSharedMemorySize, SMEM_DYN);

    k_init<<<1, 32>>>();
    k_router<<<NT / 8, 256>>>(x, Wg);
    k_scan<<<1, 32>>>(out, out_size);
    k_fill<<<NT / 256, 256>>>();
    k_gather<<<2 * NT * 128 / 256, 256>>>(x);
    k_split<ND, NH, true ><<<dim3((ND/2)*(NH/4)/256, NE), 256>>>(W1);
    k_split<NH, ND, false><<<dim3((NH/2)*(ND/4)/256, NE), 256>>>(W2);
    k_gemm<ND, true><<<dim3(64, NH / BN, NE), 512, SMEM_DYN>>>(b1);
    k_gemm<NH, false><<<dim3(64, ND / BN, NE), 512, SMEM_DYN>>>(b2);
    k_combine<<<NT * ND / 4 / 256, 256>>>(out);
}

// round 15
// speedup vs baseline: 1.4087x; 1.3817x over previous
#include <cuda_runtime.h>
#include <cuda_fp16.h>
#include <cstdint>
#include <math.h>

#define NE 8
#define NT 4096
#define ND 1024
#define NH 4096
#define SLOTP (2*NT+128)
#define BM 128
#define BN 256
#define BK 32
#define ROWW 20     // A smem words per row (16 data + 4 pad)
#define BSTR 264    // B smem words per kpair row (256 data + 8 pad)
#define STGW 9344   // words per stage (2*2560 A + 4224 B)
#define SMEM_DYN (3*STGW*4)

__device__ int      g_topi[NT*2];
__device__ float    g_topw[NT*2];
__device__ int      g_cnt[NE];
__device__ float    g_psum[NE];
__device__ int      g_off[NE+1];
__device__ int      g_cur[NE];
__device__ int      g_list[SLOTP];
__device__ int      g_slot[NT*2];
__device__ uint32_t g_AhW[(size_t)SLOTP*(ND/2)],  g_AlW[(size_t)SLOTP*(ND/2)];
__device__ uint32_t g_W1h[(size_t)NE*(ND/2)*NH];
__device__ uint32_t g_W2h[(size_t)NE*(NH/2)*ND];
__device__ uint32_t g_HhW[(size_t)SLOTP*(NH/2)], g_HlW[(size_t)SLOTP*(NH/2)];
__device__ float    g_Y[(size_t)SLOTP*ND];

__device__ __forceinline__ uint32_t smem_u32(const void* p) {
    uint32_t a;
    asm("{ .reg .u64 t; cvta.to.shared.u64 t, %1; cvt.u32.u64 %0, t; }" : "=r"(a) : "l"(p));
    return a;
}
#define CP16(d, s) asm volatile("cp.async.cg.shared.global [%0], [%1], 16;" :: "r"(d), "l"(s))
#define CPCOMMIT() asm volatile("cp.async.commit_group;" ::: "memory")
#define CPWAIT1()  asm volatile("cp.async.wait_group 1;" ::: "memory")

#define MMA(d, a0, a1, a2, a3, b0, b1) asm volatile( \
    "mma.sync.aligned.m16n8k16.row.col.f32.f16.f16.f32 " \
    "{%0,%1,%2,%3}, {%4,%5,%6,%7}, {%8,%9}, {%0,%1,%2,%3};" \
    : "+f"((d)[0]),"+f"((d)[1]),"+f"((d)[2]),"+f"((d)[3]) \
    : "r"(a0),"r"(a1),"r"(a2),"r"(a3), "r"(b0),"r"(b1))

__device__ __forceinline__ uint32_t packh(float x, float y) {
    return (uint32_t)__half_as_ushort(__float2half(x)) |
           ((uint32_t)__half_as_ushort(__float2half(y)) << 16);
}
__device__ __forceinline__ uint32_t packhlo(float x, float y) {
    float xh = __half2float(__float2half(x));
    float yh = __half2float(__float2half(y));
    return packh(x - xh, y - yh);
}

// ---------------- small kernels ----------------------------------------------
__global__ void k_init() {
    int i = threadIdx.x;
    if (i < NE) { g_cnt[i] = 0; g_psum[i] = 0.f; g_cur[i] = 0; }
}

__global__ __launch_bounds__(256) void k_router(const float* __restrict__ x,
                                                const float* __restrict__ Wg) {
    __shared__ float sW[NE * ND];
    int tid = threadIdx.x;
    for (int i = tid; i < NE * ND; i += 256) sW[i] = Wg[i];
    __syncthreads();
    int warp = tid >> 5, lane = tid & 31;
    int t = blockIdx.x * 8 + warp;
    float acc[NE];
#pragma unroll
    for (int e = 0; e < NE; e++) acc[e] = 0.f;
    const float* xr = x + (size_t)t * ND;
    for (int d = lane; d < ND; d += 32) {
        float xv = xr[d];
#pragma unroll
        for (int e = 0; e < NE; e++) acc[e] = fmaf(xv, sW[e * ND + d], acc[e]);
    }
#pragma unroll
    for (int e = 0; e < NE; e++)
#pragma unroll
        for (int o = 16; o; o >>= 1) acc[e] += __shfl_xor_sync(0xffffffffu, acc[e], o);
    if (lane == 0) {
        float mx = acc[0];
#pragma unroll
        for (int e = 1; e < NE; e++) mx = fmaxf(mx, acc[e]);
        float p[NE], Z = 0.f;
#pragma unroll
        for (int e = 0; e < NE; e++) { p[e] = expf(acc[e] - mx); Z += p[e]; }
        float inv = 1.f / Z;
#pragma unroll
        for (int e = 0; e < NE; e++) { p[e] *= inv; atomicAdd(&g_psum[e], p[e]); }
        int i0 = 0;
#pragma unroll
        for (int e = 1; e < NE; e++) if (p[e] > p[i0]) i0 = e;
        int i1 = (i0 == 0) ? 1 : 0;
#pragma unroll
        for (int e = 0; e < NE; e++) if (e != i0 && p[e] > p[i1]) i1 = e;
        float s = p[i0] + p[i1];
        g_topi[t*2] = i0; g_topi[t*2+1] = i1;
        g_topw[t*2] = p[i0] / s; g_topw[t*2+1] = p[i1] / s;
        atomicAdd(&g_cnt[i0], 1); atomicAdd(&g_cnt[i1], 1);
    }
}

__global__ void k_scan(float* __restrict__ out, int out_size) {
    if (threadIdx.x == 0) {
        int off = 0;
        for (int e = 0; e < NE; e++) { g_off[e] = off; off += g_cnt[e]; }
        g_off[NE] = off;
        float invT = 1.f / (float)NT, aux = 0.f;
        for (int e = 0; e < NE; e++) aux += ((float)g_cnt[e] * invT) * (g_psum[e] * invT);
        if (out_size > NT * ND) out[(size_t)NT * ND] = aux * (float)NE;
    }
}

__global__ void k_fill() {
    int t = blockIdx.x * blockDim.x + threadIdx.x;
    if (t >= NT) return;
#pragma unroll
    for (int k = 0; k < 2; k++) {
        int e = g_topi[t*2+k];
        int s = g_off[e] + atomicAdd(&g_cur[e], 1);
        g_list[s] = t;
        g_slot[t*2+k] = s;
    }
}

// gather + fp16 split + pair-pack x
__global__ __launch_bounds__(256) void k_gather(const float* __restrict__ x) {
    int idx = blockIdx.x * 256 + threadIdx.x;
    int slot = idx >> 7;
    int q = (idx & 127) * 8;
    int t = g_list[slot];
    const float* p = x + (size_t)t * ND + q;
    float4 v0 = *(const float4*)p;
    float4 v1 = *(const float4*)(p + 4);
    uint4 h = make_uint4(packh(v0.x, v0.y), packh(v0.z, v0.w),
                         packh(v1.x, v1.y), packh(v1.z, v1.w));
    uint4 l = make_uint4(packhlo(v0.x, v0.y), packhlo(v0.z, v0.w),
                         packhlo(v1.x, v1.y), packhlo(v1.z, v1.w));
    size_t o = (size_t)slot * (ND/2) + q/2;
    *(uint4*)&g_AhW[o] = h;
    *(uint4*)&g_AlW[o] = l;
}

// fp16 hi-only pair-pack W (device-side global selection)
template<int K, int N, bool FIRST>
__global__ __launch_bounds__(256) void k_split(const float* __restrict__ W) {
    uint32_t* __restrict__ Wh = FIRST ? g_W1h : g_W2h;
    int e = blockIdx.y;
    int idx = blockIdx.x * 256 + threadIdx.x;
    int kp = idx / (N/4);
    int nq = (idx % (N/4)) * 4;
    const float* p = W + ((size_t)e * K + 2*kp) * N + nq;
    float4 r0 = *(const float4*)p;
    float4 r1 = *(const float4*)(p + N);
    uint4 h = make_uint4(packh(r0.x, r1.x), packh(r0.y, r1.y),
                         packh(r0.z, r1.z), packh(r0.w, r1.w));
    size_t o = ((size_t)e * (K/2) + kp) * N + nq;
    *(uint4*)&Wh[o] = h;
}

// ---------------- fp16 2-pass tensor-core grouped GEMM -----------------------
// C ≈ Ah·Bh + Al·Bh  (A: 2-limb fp16; B: hi-only fp16)
template<int KDIM, bool G1>
__global__ __launch_bounds__(512) void k_gemm(const float* __restrict__ bias) {
    const int KW = KDIM / 2;
    int e = blockIdx.z;
    int ne = g_cnt[e];
    if ((int)blockIdx.x * BM >= ne) return;
    int row0 = g_off[e] + blockIdx.x * BM;
    int valid = min(BM, ne - (int)blockIdx.x * BM);
    int n0 = blockIdx.y * BN;

    extern __shared__ uint32_t sm[];
    __shared__ float sbias[BN];
    uint32_t sbase = smem_u32(sm);

    int tid = threadIdx.x, wid = tid >> 5, lane = tid & 31;
    int wm = wid & 3, wn = wid >> 2;           // 4x4 warps, warp tile 32x64
    const int ldn = G1 ? NH : ND;

    if (tid < BN) sbias[tid] = bias[(size_t)e * ldn + n0 + tid];

    const uint32_t* aH = (G1 ? g_AhW : g_HhW);
    const uint32_t* aL = (G1 ? g_AlW : g_HlW);
    const uint32_t* bH = (G1 ? g_W1h : g_W2h);

    int am = tid >> 2, aw = (tid & 3) * 4;
    const uint32_t* arH = aH + (size_t)(row0 + am) * KW + aw;
    const uint32_t* arL = aL + (size_t)(row0 + am) * KW + aw;
    int bkp = wid, bseg = lane * 8;
    const uint32_t* brH = bH + ((size_t)e * KW + bkp) * ldn + n0 + bseg;

    uint32_t aoff = (uint32_t)(am * ROWW + aw) * 4u;
    uint32_t boff = (uint32_t)(bkp * BSTR + bseg) * 4u;

    auto load_stage = [&](int s, int kc) {
        uint32_t st = sbase + (uint32_t)s * (STGW * 4u);
        CP16(st + aoff, arH + (size_t)kc * 16);
        CP16(st + 10240 + aoff, arL + (size_t)kc * 16);
        const uint32_t* pb = brH + (size_t)(kc * 16) * ldn;
        CP16(st + 20480 + boff, pb);
        CP16(st + 20480 + boff + 16, pb + 4);
    };

    float acc[2][8][4];
#pragma unroll
    for (int i = 0; i < 2; i++)
#pragma unroll
        for (int j = 0; j < 8; j++)
#pragma unroll
            for (int c = 0; c < 4; c++) acc[i][j][c] = 0.f;

    load_stage(0, 0); CPCOMMIT();
    load_stage(1, 1); CPCOMMIT();

    const int NK = KDIM / BK;
    int ks3 = 0;
    for (int k = 0; k < NK; k++) {
        CPWAIT1();
        __syncthreads();
        if (k + 2 < NK) load_stage((ks3 + 2) % 3, k + 2);
        CPCOMMIT();

        uint32_t* stg = sm + ks3 * STGW;
        uint32_t* sAh = stg;
        uint32_t* sAl = stg + 2560;
        uint32_t* sBh = stg + 5120;

#pragma unroll
        for (int ks = 0; ks < 2; ks++) {
            int kb = ks * 8;
            uint32_t Ah[2][4], Al[2][4], Bh[8][2];
#pragma unroll
            for (int mt = 0; mt < 2; mt++) {
                int r = wm * 32 + mt * 16 + (lane >> 2);
                int w0 = r * ROWW + kb + (lane & 3);
                Ah[mt][0] = sAh[w0];      Ah[mt][1] = sAh[w0 + 8*ROWW];
                Ah[mt][2] = sAh[w0 + 4];  Ah[mt][3] = sAh[w0 + 8*ROWW + 4];
                Al[mt][0] = sAl[w0];      Al[mt][1] = sAl[w0 + 8*ROWW];
                Al[mt][2] = sAl[w0 + 4];  Al[mt][3] = sAl[w0 + 8*ROWW + 4];
            }
            int kp0 = kb + (lane & 3);
#pragma unroll
            for (int nb = 0; nb < 8; nb++) {
                int n = wn * 64 + nb * 8 + (lane >> 2);
                Bh[nb][0] = sBh[kp0 * BSTR + n];
                Bh[nb][1] = sBh[(kp0 + 4) * BSTR + n];
            }
            // pass hh
#pragma unroll
            for (int mt = 0; mt < 2; mt++)
#pragma unroll
                for (int nb = 0; nb < 8; nb++)
                    MMA(acc[mt][nb], Ah[mt][0], Ah[mt][1], Ah[mt][2], Ah[mt][3],
                        Bh[nb][0], Bh[nb][1]);
            // pass lh
#pragma unroll
            for (int mt = 0; mt < 2; mt++)
#pragma unroll
                for (int nb = 0; nb < 8; nb++)
                    MMA(acc[mt][nb], Al[mt][0], Al[mt][1], Al[mt][2], Al[mt][3],
                        Bh[nb][0], Bh[nb][1]);
        }
        ks3 = (ks3 + 1) % 3;
    }

    // ---- epilogue ----
    int rb_ = lane >> 2;
    int cb = wn * 64 + (lane & 3) * 2;
#pragma unroll
    for (int mt = 0; mt < 2; mt++)
#pragma unroll
        for (int nb = 0; nb < 8; nb++) {
            int col = cb + nb * 8;
            float bv0 = sbias[col], bv1 = sbias[col + 1];
#pragma unroll
            for (int h = 0; h < 2; h++) {
                int rloc = wm * 32 + mt * 16 + h * 8 + rb_;
                if (rloc < valid) {
                    float v0 = acc[mt][nb][h*2]   + bv0;
                    float v1 = acc[mt][nb][h*2+1] + bv1;
                    if (G1) {
                        v0 = v0 / (1.f + __expf(-v0));
                        v1 = v1 / (1.f + __expf(-v1));
                        size_t go = (size_t)(row0 + rloc) * (NH/2) + (n0 + col)/2;
                        g_HhW[go] = packh(v0, v1);
                        g_HlW[go] = packhlo(v0, v1);
                    } else {
                        size_t go = (size_t)(row0 + rloc) * ND + n0 + col;
                        *(float2*)&g_Y[go] = make_float2(v0, v1);
                    }
                }
            }
        }
}

// ---------------- combine ----------------------------------------------------
__global__ __launch_bounds__(256) void k_combine(float* __restrict__ out) {
    int idx = blockIdx.x * 256 + threadIdx.x;
    int t = idx >> 8;
    int c = (idx & 255) << 2;
    float w0 = g_topw[t*2], w1 = g_topw[t*2+1];
    int s0 = g_slot[t*2], s1 = g_slot[t*2+1];
    float4 y0 = *(const float4*)&g_Y[(size_t)s0 * ND + c];
    float4 y1 = *(const float4*)&g_Y[(size_t)s1 * ND + c];
    float4 o;
    o.x = w0*y0.x + w1*y1.x; o.y = w0*y0.y + w1*y1.y;
    o.z = w0*y0.z + w1*y1.z; o.w = w0*y0.w + w1*y1.w;
    *(float4*)&out[(size_t)t * ND + c] = o;
}

// ---------------- launch -----------------------------------------------------
extern "C" void kernel_launch(void* const* d_in, const int* in_sizes, int n_in,
                              void* d_out, int out_size) {
    const float* x  = (const float*)d_in[0];
    const float* Wg = (const float*)d_in[1];
    const float* W1 = (const float*)d_in[2];
    const float* b1 = (const float*)d_in[3];
    const float* W2 = (const float*)d_in[4];
    const float* b2 = (const float*)d_in[5];
    float* out = (float*)d_out;

    cudaFuncSetAttribute(k_gemm<ND, true>,  cudaFuncAttributeMaxDynamicSharedMemorySize, SMEM_DYN);
    cudaFuncSetAttribute(k_gemm<NH, false>, cudaFuncAttributeMaxDynamicSharedMemorySize, SMEM_DYN);

    k_init<<<1, 32>>>();
    k_router<<<NT / 8, 256>>>(x, Wg);
    k_scan<<<1, 32>>>(out, out_size);
    k_fill<<<NT / 256, 256>>>();
    k_gather<<<2 * NT * 128 / 256, 256>>>(x);
    k_split<ND, NH, true ><<<dim3((ND/2)*(NH/4)/256, NE), 256>>>(W1);
    k_split<NH, ND, false><<<dim3((NH/2)*(ND/4)/256, NE), 256>>>(W2);
    k_gemm<ND, true><<<dim3(64, NH / BN, NE), 512, SMEM_DYN>>>(b1);
    k_gemm<NH, false><<<dim3(64, ND / BN, NE), 512, SMEM_DYN>>>(b2);
    k_combine<<<NT * ND / 4 / 256, 256>>>(out);
}